// round 1
// baseline (speedup 1.0000x reference)
#include <cuda_runtime.h>

#define BB   4
#define NPTS 16384
#define SS   2048
#define C1   128
#define C2   256
#define CIN  384
#define CH   256
#define ROWS (BB*NPTS)   // 65536

// Scratch (static device globals; no runtime allocation allowed)
__device__ float g_interp[(size_t)ROWS * C2];  // 67MB
__device__ float g_x[(size_t)ROWS * CH];       // 67MB
__device__ float g_stats[2 * CH];              // per-channel sum / sumsq

// ---------------------------------------------------------------------------
// Kernel 1: brute-force KNN (k=3) + inverse-distance-weighted interpolation
// One thread per query point; all S=2048 reference points staged in SMEM.
// ---------------------------------------------------------------------------
__global__ void __launch_bounds__(256) knn_interp_kernel(
    const float* __restrict__ p1,   // [B,N,3]
    const float* __restrict__ p2,   // [B,S,3]
    const float* __restrict__ pf2)  // [B,S,C2]
{
    __shared__ float sp[SS * 3];
    __shared__ float ssq[SS];
    const int b = blockIdx.y;
    const int tid = threadIdx.x;

    for (int i = tid; i < SS * 3; i += blockDim.x)
        sp[i] = p2[b * SS * 3 + i];
    __syncthreads();
    for (int i = tid; i < SS; i += blockDim.x) {
        float x = sp[3*i], y = sp[3*i+1], z = sp[3*i+2];
        ssq[i] = x*x + y*y + z*z;
    }
    __syncthreads();

    const int n = blockIdx.x * blockDim.x + tid;
    const int q = b * NPTS + n;
    const float qx = p1[q*3+0], qy = p1[q*3+1], qz = p1[q*3+2];
    const float sq1 = qx*qx + qy*qy + qz*qz;

    float d0 = 1e30f, d1 = 1e30f, d2 = 1e30f;
    int   i0 = 0,     i1 = 0,     i2 = 0;

    #pragma unroll 4
    for (int s = 0; s < SS; ++s) {
        float x = sp[3*s], y = sp[3*s+1], z = sp[3*s+2];
        float dot = fmaf(qx, x, fmaf(qy, y, qz * z));
        float d = sq1 + ssq[s] - 2.0f * dot;   // matches reference expansion
        if (d < d2) {
            if (d < d1) {
                d2 = d1; i2 = i1;
                if (d < d0) { d1 = d0; i1 = i0; d0 = d; i0 = s; }
                else        { d1 = d;  i1 = s; }
            } else { d2 = d; i2 = s; }
        }
    }

    float r0 = 1.0f / (d0 + 1e-8f);
    float r1 = 1.0f / (d1 + 1e-8f);
    float r2 = 1.0f / (d2 + 1e-8f);
    float inv = 1.0f / (r0 + r1 + r2);
    float w0 = r0 * inv, w1 = r1 * inv, w2 = r2 * inv;

    const float4* f0 = (const float4*)(pf2 + (size_t)(b * SS + i0) * C2);
    const float4* f1 = (const float4*)(pf2 + (size_t)(b * SS + i1) * C2);
    const float4* f2 = (const float4*)(pf2 + (size_t)(b * SS + i2) * C2);
    float4* out = (float4*)(g_interp + (size_t)q * C2);

    #pragma unroll 8
    for (int c = 0; c < C2 / 4; ++c) {
        float4 a = f0[c], bv = f1[c], cv = f2[c];
        float4 o;
        o.x = w0*a.x + w1*bv.x + w2*cv.x;
        o.y = w0*a.y + w1*bv.y + w2*cv.y;
        o.z = w0*a.z + w1*bv.z + w2*cv.z;
        o.w = w0*a.w + w1*bv.w + w2*cv.w;
        out[c] = o;
    }
}

// ---------------------------------------------------------------------------
// Kernel 2/5: tiled fp32 GEMM. Y[row,o] = sum_k A[row,k] * W[o,k]
// BM=128, BN=64, BK=16, 256 threads, 8x4 accum per thread.
// SPLIT=true: A row = concat(A0[row, 0:128], A1[row, 0:256])  (K=384)
// ---------------------------------------------------------------------------
template <int K, bool SPLIT>
__global__ void __launch_bounds__(256) gemm_kernel(
    const float* __restrict__ A0, const float* __restrict__ A1,
    const float* __restrict__ W, float* __restrict__ Y)
{
    constexpr int BM = 128, BN = 64, BK = 16;
    __shared__ float As[BK][BM];
    __shared__ float Ws[BK][BN];

    const int tid = threadIdx.x;
    const int rowBase = blockIdx.x * BM;
    const int colBase = blockIdx.y * BN;
    const int ty = tid >> 4;   // 0..15: rows ty*8 .. ty*8+7
    const int tx = tid & 15;   // 0..15: cols tx*4 .. tx*4+3

    // A loader mapping: row = tid>>1 (0..127), k offset = (tid&1)*8, 2 float4
    const int lar = tid >> 1;
    const int lak = (tid & 1) * 8;
    // W loader mapping: o = tid>>2 (0..63), k offset = (tid&3)*4, 1 float4
    const int lwo = tid >> 2;
    const int lwk = (tid & 3) * 4;

    float acc[8][4];
    #pragma unroll
    for (int i = 0; i < 8; ++i)
        #pragma unroll
        for (int j = 0; j < 4; ++j) acc[i][j] = 0.0f;

    #pragma unroll 1
    for (int kt = 0; kt < K / BK; ++kt) {
        // ---- load A tile (transposed into SMEM) ----
        const int kglob = kt * BK + lak;
        const float* srcA;
        if (SPLIT) {
            if (kglob < C1) srcA = A0 + (size_t)(rowBase + lar) * C1 + kglob;
            else            srcA = A1 + (size_t)(rowBase + lar) * C2 + (kglob - C1);
        } else {
            srcA = A0 + (size_t)(rowBase + lar) * K + kglob;
        }
        float4 v0 = *(const float4*)(srcA);
        float4 v1 = *(const float4*)(srcA + 4);
        As[lak+0][lar] = v0.x; As[lak+1][lar] = v0.y;
        As[lak+2][lar] = v0.z; As[lak+3][lar] = v0.w;
        As[lak+4][lar] = v1.x; As[lak+5][lar] = v1.y;
        As[lak+6][lar] = v1.z; As[lak+7][lar] = v1.w;

        // ---- load W tile (transposed into SMEM) ----
        float4 wv = *(const float4*)(W + (size_t)(colBase + lwo) * K + kt * BK + lwk);
        Ws[lwk+0][lwo] = wv.x; Ws[lwk+1][lwo] = wv.y;
        Ws[lwk+2][lwo] = wv.z; Ws[lwk+3][lwo] = wv.w;

        __syncthreads();

        #pragma unroll
        for (int kk = 0; kk < BK; ++kk) {
            float a[8], bb[4];
            *(float4*)(a)     = *(const float4*)(&As[kk][ty*8]);
            *(float4*)(a + 4) = *(const float4*)(&As[kk][ty*8 + 4]);
            *(float4*)(bb)    = *(const float4*)(&Ws[kk][tx*4]);
            #pragma unroll
            for (int i = 0; i < 8; ++i)
                #pragma unroll
                for (int j = 0; j < 4; ++j)
                    acc[i][j] = fmaf(a[i], bb[j], acc[i][j]);
        }
        __syncthreads();
    }

    #pragma unroll
    for (int i = 0; i < 8; ++i) {
        float4 v = make_float4(acc[i][0], acc[i][1], acc[i][2], acc[i][3]);
        *(float4*)(Y + (size_t)(rowBase + ty*8 + i) * CH + colBase + tx*4) = v;
    }
}

// ---------------------------------------------------------------------------
// BN stats: per-channel sum and sumsq over 65536 rows (coalesced, atomics)
// ---------------------------------------------------------------------------
__global__ void zero_stats_kernel() {
    g_stats[threadIdx.x] = 0.0f;
}

__global__ void __launch_bounds__(256) stats_kernel(const float* __restrict__ X) {
    const int c = threadIdx.x;                 // channel 0..255
    const size_t base = (size_t)blockIdx.x * 256 * CH;
    float s = 0.0f, s2 = 0.0f;
    #pragma unroll 4
    for (int r = 0; r < 256; ++r) {
        float v = X[base + (size_t)r * CH + c];
        s += v;
        s2 = fmaf(v, v, s2);
    }
    atomicAdd(&g_stats[c], s);
    atomicAdd(&g_stats[CH + c], s2);
}

// ---------------------------------------------------------------------------
// BN (training-mode stats) + ReLU, in place. Per-channel scale/bias in SMEM.
// ---------------------------------------------------------------------------
__global__ void __launch_bounds__(256) bnrelu_kernel(
    float* __restrict__ X,
    const float* __restrict__ gamma, const float* __restrict__ beta)
{
    __shared__ float sc[CH], bi[CH];
    const int t = threadIdx.x;
    {
        const float invM = 1.0f / (float)ROWS;
        float mean = g_stats[t] * invM;
        float var  = g_stats[CH + t] * invM - mean * mean;
        float s = rsqrtf(var + 1e-5f) * gamma[t];
        sc[t] = s;
        bi[t] = beta[t] - mean * s;
    }
    __syncthreads();

    const int total = ROWS * CH / 4;
    for (int i = blockIdx.x * blockDim.x + t; i < total; i += gridDim.x * blockDim.x) {
        float4 v = ((float4*)X)[i];
        int c0 = (i * 4) & (CH - 1);
        v.x = fmaxf(fmaf(v.x, sc[c0+0], bi[c0+0]), 0.0f);
        v.y = fmaxf(fmaf(v.y, sc[c0+1], bi[c0+1]), 0.0f);
        v.z = fmaxf(fmaf(v.z, sc[c0+2], bi[c0+2]), 0.0f);
        v.w = fmaxf(fmaf(v.w, sc[c0+3], bi[c0+3]), 0.0f);
        ((float4*)X)[i] = v;
    }
}

// ---------------------------------------------------------------------------
// Launcher (graph-capturable: kernel launches only)
// ---------------------------------------------------------------------------
extern "C" void kernel_launch(void* const* d_in, const int* in_sizes, int n_in,
                              void* d_out, int out_size)
{
    const float* p1     = (const float*)d_in[0];
    const float* p2     = (const float*)d_in[1];
    const float* pf1    = (const float*)d_in[2];
    const float* pf2    = (const float*)d_in[3];
    const float* W1     = (const float*)d_in[4];
    const float* gamma1 = (const float*)d_in[5];
    const float* beta1  = (const float*)d_in[6];
    const float* W2     = (const float*)d_in[7];
    const float* gamma2 = (const float*)d_in[8];
    const float* beta2  = (const float*)d_in[9];
    float* out = (float*)d_out;

    float* interp_p = nullptr;
    float* x_p = nullptr;
    cudaGetSymbolAddress((void**)&interp_p, g_interp);
    cudaGetSymbolAddress((void**)&x_p, g_x);

    // 1. KNN + interpolation
    knn_interp_kernel<<<dim3(NPTS / 256, BB), 256>>>(p1, p2, pf2);

    // 2. layer 1: GEMM over concat(pf1, interp) -> g_x (pre-activation)
    gemm_kernel<CIN, true><<<dim3(ROWS / 128, CH / 64), 256>>>(pf1, interp_p, W1, x_p);

    // 3. BN stats + BN+ReLU in place
    zero_stats_kernel<<<1, 2 * CH>>>();
    stats_kernel<<<256, 256>>>(x_p);
    bnrelu_kernel<<<2048, 256>>>(x_p, gamma1, beta1);

    // 4. layer 2: GEMM -> d_out (pre-activation)
    gemm_kernel<CH, false><<<dim3(ROWS / 128, CH / 64), 256>>>(x_p, nullptr, W2, out);

    // 5. BN stats + BN+ReLU in place on d_out
    zero_stats_kernel<<<1, 2 * CH>>>();
    stats_kernel<<<256, 256>>>(out);
    bnrelu_kernel<<<2048, 256>>>(out, gamma2, beta2);
}

// round 4
// speedup vs baseline: 1.3201x; 1.3201x over previous
#include <cuda_runtime.h>
#include <cuda_bf16.h>
#include <cstdint>

#define BB   4
#define NPTS 16384
#define SSZ  2048
#define C1   128
#define C2   256
#define CIN  384
#define CH   256
#define ROWS (BB*NPTS)   // 65536
#define K1   (3*CIN)     // 1152  triple-plane K for layer 1
#define K2   (3*CH)      // 768   triple-plane K for layer 2

// ---------------------------------------------------------------------------
// Scratch (static device globals; no runtime allocation allowed)
// A-side rows: [hi(0:K) | hi(0:K) | lo(0:K)]
// W-side rows: [hi(0:K) | lo(0:K) | hi(0:K)]
//   => sum over K_eff = Ahi*Whi + Ahi*Wlo + Alo*Whi
// ---------------------------------------------------------------------------
__device__ __nv_bfloat16 g_a1[(size_t)ROWS * K1];   // 151 MB
__device__ __nv_bfloat16 g_x [(size_t)ROWS * K2];   // 100 MB
__device__ float         g_y [(size_t)ROWS * CH];   // 67 MB
__device__ __nv_bfloat16 g_w1[CH * K1];
__device__ __nv_bfloat16 g_w2[CH * K2];
__device__ float g_stats1[2 * CH];
__device__ float g_stats2[2 * CH];

// ---------------------------------------------------------------------------
// PTX helpers (compute_103-safe: no tcgen05 / TMEM)
// ---------------------------------------------------------------------------
__device__ __forceinline__ uint32_t smem_u32(const void* p) {
    uint32_t a;
    asm("{ .reg .u64 t; cvta.to.shared.u64 t, %1; cvt.u32.u64 %0, t; }"
        : "=r"(a) : "l"(p));
    return a;
}

__device__ __forceinline__ void cp16(uint32_t dst, const void* src) {
    asm volatile("cp.async.cg.shared.global [%0], [%1], 16;" :: "r"(dst), "l"(src));
}

__device__ __forceinline__ void ldsm_x4(uint32_t* r, uint32_t addr) {
    asm volatile("ldmatrix.sync.aligned.m8n8.x4.shared.b16 {%0,%1,%2,%3}, [%4];"
        : "=r"(r[0]), "=r"(r[1]), "=r"(r[2]), "=r"(r[3]) : "r"(addr));
}

__device__ __forceinline__ void mma16816(float* d, const uint32_t* a, const uint32_t* b) {
    asm volatile(
        "mma.sync.aligned.m16n8k16.row.col.f32.bf16.bf16.f32 "
        "{%0,%1,%2,%3}, {%4,%5,%6,%7}, {%8,%9}, {%0,%1,%2,%3};"
        : "+f"(d[0]), "+f"(d[1]), "+f"(d[2]), "+f"(d[3])
        : "r"(a[0]), "r"(a[1]), "r"(a[2]), "r"(a[3]), "r"(b[0]), "r"(b[1]));
}

__device__ __forceinline__ void split_bf16(float o, __nv_bfloat16& h, __nv_bfloat16& l) {
    h = __float2bfloat16(o);
    l = __float2bfloat16(o - __bfloat162float(h));
}

// ---------------------------------------------------------------------------
// Kernel 1: brute-force KNN (k=3) + IDW interpolation.
// Distance arithmetic identical to the R1-passing version.
// Writes interp features (cols C1..C1+C2) into the 3 planes of g_a1.
// ---------------------------------------------------------------------------
__global__ void __launch_bounds__(256) knn_interp_kernel(
    const float* __restrict__ p1, const float* __restrict__ p2,
    const float* __restrict__ pf2, __nv_bfloat16* __restrict__ a1)
{
    __shared__ float4 sp[SSZ];
    const int b = blockIdx.y;
    const int tid = threadIdx.x;

    for (int i = tid; i < SSZ; i += 256) {
        float x = p2[(b * SSZ + i) * 3 + 0];
        float y = p2[(b * SSZ + i) * 3 + 1];
        float z = p2[(b * SSZ + i) * 3 + 2];
        sp[i] = make_float4(x, y, z, x*x + y*y + z*z);
    }
    __syncthreads();

    const int n = blockIdx.x * 256 + tid;
    const int q = b * NPTS + n;
    const float qx = p1[q*3+0], qy = p1[q*3+1], qz = p1[q*3+2];
    const float sq1 = qx*qx + qy*qy + qz*qz;

    float d0 = 1e30f, d1 = 1e30f, d2 = 1e30f;
    int   i0 = 0,     i1 = 0,     i2 = 0;

    #pragma unroll 4
    for (int s = 0; s < SSZ; ++s) {
        float4 t = sp[s];
        float dot = fmaf(qx, t.x, fmaf(qy, t.y, qz * t.z));
        float d = sq1 + t.w - 2.0f * dot;          // same arithmetic as R1
        if (d < d2) {
            if (d < d1) {
                d2 = d1; i2 = i1;
                if (d < d0) { d1 = d0; i1 = i0; d0 = d; i0 = s; }
                else        { d1 = d;  i1 = s; }
            } else { d2 = d; i2 = s; }
        }
    }

    float r0 = 1.0f / (d0 + 1e-8f);
    float r1 = 1.0f / (d1 + 1e-8f);
    float r2 = 1.0f / (d2 + 1e-8f);
    float inv = 1.0f / (r0 + r1 + r2);
    float w0 = r0 * inv, w1 = r1 * inv, w2 = r2 * inv;

    const float4* f0 = (const float4*)(pf2 + (size_t)(b * SSZ + i0) * C2);
    const float4* f1 = (const float4*)(pf2 + (size_t)(b * SSZ + i1) * C2);
    const float4* f2 = (const float4*)(pf2 + (size_t)(b * SSZ + i2) * C2);
    __nv_bfloat16* base = a1 + (size_t)q * K1 + C1;

    #pragma unroll 8
    for (int c = 0; c < C2 / 4; ++c) {
        float4 a = f0[c], bv = f1[c], cv = f2[c];
        float o[4];
        o[0] = w0*a.x + w1*bv.x + w2*cv.x;
        o[1] = w0*a.y + w1*bv.y + w2*cv.y;
        o[2] = w0*a.z + w1*bv.z + w2*cv.z;
        o[3] = w0*a.w + w1*bv.w + w2*cv.w;
        __nv_bfloat16 h[4], l[4];
        #pragma unroll
        for (int j = 0; j < 4; ++j) split_bf16(o[j], h[j], l[j]);
        __nv_bfloat162 hh0 = __halves2bfloat162(h[0], h[1]);
        __nv_bfloat162 hh1 = __halves2bfloat162(h[2], h[3]);
        *(__nv_bfloat162*)(base + c*4)            = hh0;
        *(__nv_bfloat162*)(base + c*4 + 2)        = hh1;
        *(__nv_bfloat162*)(base + CIN + c*4)      = hh0;
        *(__nv_bfloat162*)(base + CIN + c*4 + 2)  = hh1;
        *(__nv_bfloat162*)(base + 2*CIN + c*4)     = __halves2bfloat162(l[0], l[1]);
        *(__nv_bfloat162*)(base + 2*CIN + c*4 + 2) = __halves2bfloat162(l[2], l[3]);
    }
}

// ---------------------------------------------------------------------------
// pf1 -> triple-plane cols [0,128) of g_a1
// ---------------------------------------------------------------------------
__global__ void __launch_bounds__(256) conv_pf1_kernel(
    const float* __restrict__ pf1, __nv_bfloat16* __restrict__ a1)
{
    int i = blockIdx.x * 256 + threadIdx.x;      // float4 index over ROWS*C1/4
    int row = i >> 5;
    int c4 = (i & 31) * 4;
    float4 v = ((const float4*)pf1)[i];
    float o[4] = {v.x, v.y, v.z, v.w};
    __nv_bfloat16 h[4], l[4];
    #pragma unroll
    for (int j = 0; j < 4; ++j) split_bf16(o[j], h[j], l[j]);
    __nv_bfloat16* base = a1 + (size_t)row * K1 + c4;
    __nv_bfloat162 hh0 = __halves2bfloat162(h[0], h[1]);
    __nv_bfloat162 hh1 = __halves2bfloat162(h[2], h[3]);
    *(__nv_bfloat162*)(base)               = hh0;
    *(__nv_bfloat162*)(base + 2)           = hh1;
    *(__nv_bfloat162*)(base + CIN)         = hh0;
    *(__nv_bfloat162*)(base + CIN + 2)     = hh1;
    *(__nv_bfloat162*)(base + 2*CIN)       = __halves2bfloat162(l[0], l[1]);
    *(__nv_bfloat162*)(base + 2*CIN + 2)   = __halves2bfloat162(l[2], l[3]);
}

// ---------------------------------------------------------------------------
// W -> triple-plane [hi | lo | hi]
// ---------------------------------------------------------------------------
__global__ void __launch_bounds__(256) conv_w_kernel(
    const float* __restrict__ W, __nv_bfloat16* __restrict__ out, int Kdim, int n)
{
    int i = blockIdx.x * 256 + threadIdx.x;
    if (i < n) {
        int o = i / Kdim, k = i % Kdim;
        float w = W[i];
        __nv_bfloat16 h, l;
        split_bf16(w, h, l);
        __nv_bfloat16* base = out + (size_t)o * (3 * Kdim) + k;
        base[0]        = h;
        base[Kdim]     = l;
        base[2 * Kdim] = h;
    }
}

// ---------------------------------------------------------------------------
// Plain bf16 pipelined GEMM over K_eff: Y[row,o] = sum_k A[row,k]*W[o,k]
// CTA: M=128 x N=256, 512 threads (16 warps 2x8), warp tile 64x32.
// k-chunk 64 elems (128B), LD=144, 3-stage cp.async.
// ---------------------------------------------------------------------------
template <int KE>
__global__ void __launch_bounds__(512, 1) gemm_bf16_kernel(
    const __nv_bfloat16* __restrict__ A, const __nv_bfloat16* __restrict__ W,
    float* __restrict__ Y)
{
    constexpr int NC = KE / 64;          // k chunks
    constexpr int KB = KE * 2;           // global row stride bytes
    constexpr int LD = 144;              // smem row stride bytes (128 + 16 pad)
    constexpr int A_SZ = 128 * LD;       // 18432
    constexpr int W_SZ = 256 * LD;       // 36864
    constexpr int STAGE = A_SZ + W_SZ;   // 55296

    extern __shared__ char smem[];
    const uint32_t sb = smem_u32(smem);
    const int tid  = threadIdx.x;
    const int wid  = tid >> 5;
    const int lane = tid & 31;
    const int rowBase = blockIdx.x * 128;

    const int warp_m = wid & 1;          // 64 rows each
    const int warp_n = wid >> 1;         // 32 cols each

    const char* bA = (const char*)A + (size_t)rowBase * KB;
    const char* bW = (const char*)W;

    float acc[4][4][4];
    #pragma unroll
    for (int i = 0; i < 4; ++i)
        #pragma unroll
        for (int j = 0; j < 4; ++j)
            #pragma unroll
            for (int k = 0; k < 4; ++k) acc[i][j][k] = 0.0f;

    auto load_chunk = [&](int ck, int s) {
        if (ck < NC) {
            const uint32_t st = sb + (uint32_t)s * STAGE;
            const int cko = ck * 128;                    // 64 bf16 = 128 bytes
            #pragma unroll
            for (int j = 0; j < 2; ++j) {                // A: 128 rows x 8 = 1024
                int v = tid + j * 512;
                int row = v >> 3, c = v & 7;
                cp16(st + row * LD + c * 16, bA + (size_t)row * KB + cko + c * 16);
            }
            #pragma unroll
            for (int j = 0; j < 4; ++j) {                // W: 256 rows x 8 = 2048
                int v = tid + j * 512;
                int row = v >> 3, c = v & 7;
                cp16(st + A_SZ + row * LD + c * 16, bW + (size_t)row * KB + cko + c * 16);
            }
        }
        asm volatile("cp.async.commit_group;" ::: "memory");
    };

    load_chunk(0, 0);
    load_chunk(1, 1);
    load_chunk(2, 2);

    // ldmatrix lane addressing
    const int a_row = (lane & 15);
    const int a_k8  = (lane >> 4) << 3;
    const int b_row = (lane & 7) + ((lane >> 4) << 3);
    const int b_k8  = ((lane >> 3) & 1) << 3;

    for (int ck = 0; ck < NC; ++ck) {
        const int s = ck % 3;
        asm volatile("cp.async.wait_group 2;" ::: "memory");
        __syncthreads();

        const uint32_t aA = sb + (uint32_t)s * STAGE;
        const uint32_t aW = aA + A_SZ;

        #pragma unroll
        for (int kk = 0; kk < 4; ++kk) {
            const uint32_t kbA = (uint32_t)((kk * 16 + a_k8) * 2);
            const uint32_t kbB = (uint32_t)((kk * 16 + b_k8) * 2);

            uint32_t bb[8];
            #pragma unroll
            for (int g = 0; g < 2; ++g) {
                uint32_t nn = (uint32_t)(warp_n * 32 + g * 16 + b_row);
                ldsm_x4(bb + g * 4, aW + nn * LD + kbB);
            }
            #pragma unroll
            for (int mt = 0; mt < 4; ++mt) {
                uint32_t m = (uint32_t)(warp_m * 64 + mt * 16 + a_row);
                uint32_t aa[4];
                ldsm_x4(aa, aA + m * LD + kbA);
                #pragma unroll
                for (int nt = 0; nt < 4; ++nt)
                    mma16816(acc[mt][nt], aa, bb + nt * 2);
            }
        }

        __syncthreads();
        load_chunk(ck + 3, s);
    }

    // Epilogue: write fp32 accumulators
    const int er = lane >> 2;
    const int ec = (lane & 3) * 2;
    #pragma unroll
    for (int mt = 0; mt < 4; ++mt) {
        const int row = rowBase + warp_m * 64 + mt * 16 + er;
        #pragma unroll
        for (int nt = 0; nt < 4; ++nt) {
            const int col = warp_n * 32 + nt * 8 + ec;
            *(float2*)(Y + (size_t)row * CH + col) =
                make_float2(acc[mt][nt][0], acc[mt][nt][1]);
            *(float2*)(Y + (size_t)(row + 8) * CH + col) =
                make_float2(acc[mt][nt][2], acc[mt][nt][3]);
        }
    }
}

// ---------------------------------------------------------------------------
// BN stats: 512 blocks x 128 rows, float4, SMEM reduce, 2 atomics/ch/block
// ---------------------------------------------------------------------------
__global__ void __launch_bounds__(256) zero_stats_kernel() {
    g_stats1[threadIdx.x] = 0.0f;
    g_stats2[threadIdx.x] = 0.0f;
    g_stats1[256 + threadIdx.x] = 0.0f;
    g_stats2[256 + threadIdx.x] = 0.0f;
}

__global__ void __launch_bounds__(256) stats_kernel(const float* __restrict__ X,
                                                    float* __restrict__ stats)
{
    __shared__ float rs[4][CH];
    __shared__ float rq[4][CH];
    const int tid = threadIdx.x;
    const int quad = tid >> 6;
    const int c4 = (tid & 63) * 4;
    const float* base = X + (size_t)blockIdx.x * 128 * CH;

    float4 s  = make_float4(0, 0, 0, 0);
    float4 s2 = make_float4(0, 0, 0, 0);
    #pragma unroll 8
    for (int i = 0; i < 32; ++i) {
        float4 v = *(const float4*)(base + (size_t)(quad * 32 + i) * CH + c4);
        s.x += v.x; s.y += v.y; s.z += v.z; s.w += v.w;
        s2.x = fmaf(v.x, v.x, s2.x); s2.y = fmaf(v.y, v.y, s2.y);
        s2.z = fmaf(v.z, v.z, s2.z); s2.w = fmaf(v.w, v.w, s2.w);
    }
    *(float4*)&rs[quad][c4] = s;
    *(float4*)&rq[quad][c4] = s2;
    __syncthreads();
    {
        const int c = tid;
        float a = rs[0][c] + rs[1][c] + rs[2][c] + rs[3][c];
        float b = rq[0][c] + rq[1][c] + rq[2][c] + rq[3][c];
        atomicAdd(&stats[c], a);
        atomicAdd(&stats[CH + c], b);
    }
}

// ---------------------------------------------------------------------------
// BN+ReLU, output triple-plane bf16 (layer1 -> layer2 input)
// ---------------------------------------------------------------------------
__global__ void __launch_bounds__(256) bnrelu_split_kernel(
    const float* __restrict__ Y,
    const float* __restrict__ gamma, const float* __restrict__ beta,
    __nv_bfloat16* __restrict__ X)
{
    __shared__ float sc[CH], bi[CH];
    const int t = threadIdx.x;
    {
        const float invM = 1.0f / (float)ROWS;
        float mean = g_stats1[t] * invM;
        float var  = g_stats1[CH + t] * invM - mean * mean;
        float s = rsqrtf(var + 1e-5f) * gamma[t];
        sc[t] = s;
        bi[t] = beta[t] - mean * s;
    }
    __syncthreads();

    const int total = ROWS * CH / 4;
    for (int i = blockIdx.x * 256 + t; i < total; i += gridDim.x * 256) {
        float4 v = ((const float4*)Y)[i];
        int row = i >> 6;                 // 64 float4 per row
        int c0 = (i & 63) * 4;
        float o[4];
        o[0] = fmaxf(fmaf(v.x, sc[c0+0], bi[c0+0]), 0.0f);
        o[1] = fmaxf(fmaf(v.y, sc[c0+1], bi[c0+1]), 0.0f);
        o[2] = fmaxf(fmaf(v.z, sc[c0+2], bi[c0+2]), 0.0f);
        o[3] = fmaxf(fmaf(v.w, sc[c0+3], bi[c0+3]), 0.0f);
        __nv_bfloat16 h[4], l[4];
        #pragma unroll
        for (int j = 0; j < 4; ++j) split_bf16(o[j], h[j], l[j]);
        __nv_bfloat16* base = X + (size_t)row * K2 + c0;
        __nv_bfloat162 hh0 = __halves2bfloat162(h[0], h[1]);
        __nv_bfloat162 hh1 = __halves2bfloat162(h[2], h[3]);
        *(__nv_bfloat162*)(base)              = hh0;
        *(__nv_bfloat162*)(base + 2)          = hh1;
        *(__nv_bfloat162*)(base + CH)         = hh0;
        *(__nv_bfloat162*)(base + CH + 2)     = hh1;
        *(__nv_bfloat162*)(base + 2*CH)       = __halves2bfloat162(l[0], l[1]);
        *(__nv_bfloat162*)(base + 2*CH + 2)   = __halves2bfloat162(l[2], l[3]);
    }
}

// ---------------------------------------------------------------------------
// BN+ReLU in place (layer2 final, fp32)
// ---------------------------------------------------------------------------
__global__ void __launch_bounds__(256) bnrelu_inplace_kernel(
    float* __restrict__ X,
    const float* __restrict__ gamma, const float* __restrict__ beta)
{
    __shared__ float sc[CH], bi[CH];
    const int t = threadIdx.x;
    {
        const float invM = 1.0f / (float)ROWS;
        float mean = g_stats2[t] * invM;
        float var  = g_stats2[CH + t] * invM - mean * mean;
        float s = rsqrtf(var + 1e-5f) * gamma[t];
        sc[t] = s;
        bi[t] = beta[t] - mean * s;
    }
    __syncthreads();

    const int total = ROWS * CH / 4;
    for (int i = blockIdx.x * 256 + t; i < total; i += gridDim.x * 256) {
        float4 v = ((float4*)X)[i];
        int c0 = (i * 4) & (CH - 1);
        v.x = fmaxf(fmaf(v.x, sc[c0+0], bi[c0+0]), 0.0f);
        v.y = fmaxf(fmaf(v.y, sc[c0+1], bi[c0+1]), 0.0f);
        v.z = fmaxf(fmaf(v.z, sc[c0+2], bi[c0+2]), 0.0f);
        v.w = fmaxf(fmaf(v.w, sc[c0+3], bi[c0+3]), 0.0f);
        ((float4*)X)[i] = v;
    }
}

// ---------------------------------------------------------------------------
// Launcher (graph-capturable)
// ---------------------------------------------------------------------------
extern "C" void kernel_launch(void* const* d_in, const int* in_sizes, int n_in,
                              void* d_out, int out_size)
{
    const float* p1     = (const float*)d_in[0];
    const float* p2     = (const float*)d_in[1];
    const float* pf1    = (const float*)d_in[2];
    const float* pf2    = (const float*)d_in[3];
    const float* W1     = (const float*)d_in[4];
    const float* gamma1 = (const float*)d_in[5];
    const float* beta1  = (const float*)d_in[6];
    const float* W2     = (const float*)d_in[7];
    const float* gamma2 = (const float*)d_in[8];
    const float* beta2  = (const float*)d_in[9];
    float* out = (float*)d_out;

    __nv_bfloat16 *a1, *x, *w1, *w2;
    float *y, *st1, *st2;
    cudaGetSymbolAddress((void**)&a1, g_a1);
    cudaGetSymbolAddress((void**)&x,  g_x);
    cudaGetSymbolAddress((void**)&w1, g_w1);
    cudaGetSymbolAddress((void**)&w2, g_w2);
    cudaGetSymbolAddress((void**)&y,  g_y);
    cudaGetSymbolAddress((void**)&st1, g_stats1);
    cudaGetSymbolAddress((void**)&st2, g_stats2);

    const int GEMM_SMEM = 3 * 55296;   // 165888 bytes
    cudaFuncSetAttribute(gemm_bf16_kernel<K1>,
                         cudaFuncAttributeMaxDynamicSharedMemorySize, GEMM_SMEM);
    cudaFuncSetAttribute(gemm_bf16_kernel<K2>,
                         cudaFuncAttributeMaxDynamicSharedMemorySize, GEMM_SMEM);

    // Prep
    zero_stats_kernel<<<1, 256>>>();
    conv_w_kernel<<<(CH * CIN + 255) / 256, 256>>>(W1, w1, CIN, CH * CIN);
    conv_w_kernel<<<(CH * CH + 255) / 256, 256>>>(W2, w2, CH, CH * CH);
    conv_pf1_kernel<<<ROWS * C1 / 4 / 256, 256>>>(pf1, a1);
    knn_interp_kernel<<<dim3(NPTS / 256, BB), 256>>>(p1, p2, pf2, a1);

    // Layer 1
    gemm_bf16_kernel<K1><<<ROWS / 128, 512, GEMM_SMEM>>>(a1, w1, y);
    stats_kernel<<<512, 256>>>(y, st1);
    bnrelu_split_kernel<<<2048, 256>>>(y, gamma1, beta1, x);

    // Layer 2
    gemm_bf16_kernel<K2><<<ROWS / 128, 512, GEMM_SMEM>>>(x, w2, out);
    stats_kernel<<<512, 256>>>(out, st2);
    bnrelu_inplace_kernel<<<2048, 256>>>(out, gamma2, beta2);
}

// round 6
// speedup vs baseline: 1.4845x; 1.1245x over previous
#include <cuda_runtime.h>
#include <cuda_bf16.h>
#include <cstdint>

#define BB   4
#define NPTS 16384
#define SSZ  2048
#define C1   128
#define C2   256
#define CIN  384
#define CH   256
#define ROWS (BB*NPTS)   // 65536

// ---------------------------------------------------------------------------
// Scratch. A-side: 2 planes per row [hi(K) | lo(K)].
// W-side: 3 planes per row [hi(K) | lo(K) | hi(K)].
// GEMM chunk map: ck in [0,KC): Ahi*Whi; [KC,2KC): Ahi*Wlo; [2KC,3KC): Alo*Whi.
// ---------------------------------------------------------------------------
__device__ __nv_bfloat16 g_a1[(size_t)ROWS * 2 * CIN];  // 100 MB
__device__ __nv_bfloat16 g_x [(size_t)ROWS * 2 * CH];   // 67 MB
__device__ float         g_y [(size_t)ROWS * CH];       // 67 MB
__device__ __nv_bfloat16 g_w1[CH * 3 * CIN];
__device__ __nv_bfloat16 g_w2[CH * 3 * CH];
__device__ float g_stats1[2 * CH];
__device__ float g_stats2[2 * CH];

// ---------------------------------------------------------------------------
// PTX helpers (compute_103-safe)
// ---------------------------------------------------------------------------
__device__ __forceinline__ uint32_t smem_u32(const void* p) {
    uint32_t a;
    asm("{ .reg .u64 t; cvta.to.shared.u64 t, %1; cvt.u32.u64 %0, t; }"
        : "=r"(a) : "l"(p));
    return a;
}

__device__ __forceinline__ void cp16(uint32_t dst, const void* src) {
    asm volatile("cp.async.cg.shared.global [%0], [%1], 16;" :: "r"(dst), "l"(src));
}

__device__ __forceinline__ void ldsm_x4(uint32_t* r, uint32_t addr) {
    asm volatile("ldmatrix.sync.aligned.m8n8.x4.shared.b16 {%0,%1,%2,%3}, [%4];"
        : "=r"(r[0]), "=r"(r[1]), "=r"(r[2]), "=r"(r[3]) : "r"(addr));
}

__device__ __forceinline__ void mma16816(float* d, const uint32_t* a, const uint32_t* b) {
    asm volatile(
        "mma.sync.aligned.m16n8k16.row.col.f32.bf16.bf16.f32 "
        "{%0,%1,%2,%3}, {%4,%5,%6,%7}, {%8,%9}, {%0,%1,%2,%3};"
        : "+f"(d[0]), "+f"(d[1]), "+f"(d[2]), "+f"(d[3])
        : "r"(a[0]), "r"(a[1]), "r"(a[2]), "r"(a[3]), "r"(b[0]), "r"(b[1]));
}

__device__ __forceinline__ void split_bf16(float o, __nv_bfloat16& h, __nv_bfloat16& l) {
    h = __float2bfloat16(o);
    l = __float2bfloat16(o - __bfloat162float(h));
}

// ---------------------------------------------------------------------------
// W1 -> 3-plane [hi|lo|hi], plus zero both stats arrays (block 0).
// ---------------------------------------------------------------------------
__global__ void __launch_bounds__(256) conv_w1_zero_kernel(
    const float* __restrict__ W, __nv_bfloat16* __restrict__ out)
{
    if (blockIdx.x == 0) {
        g_stats1[threadIdx.x] = 0.0f;
        g_stats1[256 + threadIdx.x] = 0.0f;
        g_stats2[threadIdx.x] = 0.0f;
        g_stats2[256 + threadIdx.x] = 0.0f;
    }
    int i = blockIdx.x * 256 + threadIdx.x;
    if (i < CH * CIN) {
        int o = i / CIN, k = i % CIN;
        float w = W[i];
        __nv_bfloat16 h, l;
        split_bf16(w, h, l);
        __nv_bfloat16* base = out + (size_t)o * (3 * CIN) + k;
        base[0]       = h;
        base[CIN]     = l;
        base[2 * CIN] = h;
    }
}

__global__ void __launch_bounds__(256) conv_w2_kernel(
    const float* __restrict__ W, __nv_bfloat16* __restrict__ out)
{
    int i = blockIdx.x * 256 + threadIdx.x;
    if (i < CH * CH) {
        int o = i / CH, k = i % CH;
        float w = W[i];
        __nv_bfloat16 h, l;
        split_bf16(w, h, l);
        __nv_bfloat16* base = out + (size_t)o * (3 * CH) + k;
        base[0]      = h;
        base[CH]     = l;
        base[2 * CH] = h;
    }
}

// ---------------------------------------------------------------------------
// pf1 -> 2-plane cols [0,128) of g_a1  (row stride 2*CIN elems)
// ---------------------------------------------------------------------------
__global__ void __launch_bounds__(256) conv_pf1_kernel(
    const float* __restrict__ pf1, __nv_bfloat16* __restrict__ a1)
{
    int i = blockIdx.x * 256 + threadIdx.x;      // float4 index over ROWS*C1/4
    int row = i >> 5;
    int c4 = (i & 31) * 4;
    float4 v = ((const float4*)pf1)[i];
    float o[4] = {v.x, v.y, v.z, v.w};
    __nv_bfloat16 h[4], l[4];
    #pragma unroll
    for (int j = 0; j < 4; ++j) split_bf16(o[j], h[j], l[j]);
    __nv_bfloat16* base = a1 + (size_t)row * (2 * CIN) + c4;
    *(__nv_bfloat162*)(base)           = __halves2bfloat162(h[0], h[1]);
    *(__nv_bfloat162*)(base + 2)       = __halves2bfloat162(h[2], h[3]);
    *(__nv_bfloat162*)(base + CIN)     = __halves2bfloat162(l[0], l[1]);
    *(__nv_bfloat162*)(base + CIN + 2) = __halves2bfloat162(l[2], l[3]);
}

// ---------------------------------------------------------------------------
// KNN (k=3) + IDW interpolation -> 2-plane cols [128,384) of g_a1
// ---------------------------------------------------------------------------
__global__ void __launch_bounds__(256) knn_interp_kernel(
    const float* __restrict__ p1, const float* __restrict__ p2,
    const float* __restrict__ pf2, __nv_bfloat16* __restrict__ a1)
{
    __shared__ float4 sp[SSZ];
    const int b = blockIdx.y;
    const int tid = threadIdx.x;

    for (int i = tid; i < SSZ; i += 256) {
        float x = p2[(b * SSZ + i) * 3 + 0];
        float y = p2[(b * SSZ + i) * 3 + 1];
        float z = p2[(b * SSZ + i) * 3 + 2];
        sp[i] = make_float4(x, y, z, x*x + y*y + z*z);
    }
    __syncthreads();

    const int n = blockIdx.x * 256 + tid;
    const int q = b * NPTS + n;
    const float qx = p1[q*3+0], qy = p1[q*3+1], qz = p1[q*3+2];
    const float sq1 = qx*qx + qy*qy + qz*qz;

    float d0 = 1e30f, d1 = 1e30f, d2 = 1e30f;
    int   i0 = 0,     i1 = 0,     i2 = 0;

    #pragma unroll 4
    for (int s = 0; s < SSZ; ++s) {
        float4 t = sp[s];
        float dot = fmaf(qx, t.x, fmaf(qy, t.y, qz * t.z));
        float d = sq1 + t.w - 2.0f * dot;
        if (d < d2) {
            if (d < d1) {
                d2 = d1; i2 = i1;
                if (d < d0) { d1 = d0; i1 = i0; d0 = d; i0 = s; }
                else        { d1 = d;  i1 = s; }
            } else { d2 = d; i2 = s; }
        }
    }

    float r0 = 1.0f / (d0 + 1e-8f);
    float r1 = 1.0f / (d1 + 1e-8f);
    float r2 = 1.0f / (d2 + 1e-8f);
    float inv = 1.0f / (r0 + r1 + r2);
    float w0 = r0 * inv, w1 = r1 * inv, w2 = r2 * inv;

    const float4* f0 = (const float4*)(pf2 + (size_t)(b * SSZ + i0) * C2);
    const float4* f1 = (const float4*)(pf2 + (size_t)(b * SSZ + i1) * C2);
    const float4* f2 = (const float4*)(pf2 + (size_t)(b * SSZ + i2) * C2);
    __nv_bfloat16* base = a1 + (size_t)q * (2 * CIN) + C1;

    #pragma unroll 8
    for (int c = 0; c < C2 / 4; ++c) {
        float4 a = f0[c], bv = f1[c], cv = f2[c];
        float o[4];
        o[0] = w0*a.x + w1*bv.x + w2*cv.x;
        o[1] = w0*a.y + w1*bv.y + w2*cv.y;
        o[2] = w0*a.z + w1*bv.z + w2*cv.z;
        o[3] = w0*a.w + w1*bv.w + w2*cv.w;
        __nv_bfloat16 h[4], l[4];
        #pragma unroll
        for (int j = 0; j < 4; ++j) split_bf16(o[j], h[j], l[j]);
        *(__nv_bfloat162*)(base + c*4)           = __halves2bfloat162(h[0], h[1]);
        *(__nv_bfloat162*)(base + c*4 + 2)       = __halves2bfloat162(h[2], h[3]);
        *(__nv_bfloat162*)(base + CIN + c*4)     = __halves2bfloat162(l[0], l[1]);
        *(__nv_bfloat162*)(base + CIN + c*4 + 2) = __halves2bfloat162(l[2], l[3]);
    }
}

// ---------------------------------------------------------------------------
// bf16 pipelined GEMM, plane-mapped chunks, fused BN-stats epilogue.
// Y[row,o] = sum over 3 plane products; CTA 128x256, 512 thr, warp tile 64x32.
// ---------------------------------------------------------------------------
template <int K>
__global__ void __launch_bounds__(512, 1) gemm_fused_kernel(
    const __nv_bfloat16* __restrict__ A, const __nv_bfloat16* __restrict__ W,
    float* __restrict__ Y, float* __restrict__ stats)
{
    constexpr int KC  = K / 64;          // chunks per plane product
    constexpr int NCC = 3 * KC;          // total chunks
    constexpr int KB_A = 4 * K;          // A row stride bytes (hi+lo)
    constexpr int KB_W = 6 * K;          // W row stride bytes (3 planes)
    constexpr int LD = 144;              // smem row stride bytes
    constexpr int A_SZ = 128 * LD;       // 18432
    constexpr int W_SZ = 256 * LD;       // 36864
    constexpr int STAGE = A_SZ + W_SZ;   // 55296

    extern __shared__ char smem[];
    const uint32_t sb = smem_u32(smem);
    const int tid  = threadIdx.x;
    const int wid  = tid >> 5;
    const int lane = tid & 31;
    const int rowBase = blockIdx.x * 128;

    const int warp_m = wid & 1;
    const int warp_n = wid >> 1;

    const char* bA = (const char*)A + (size_t)rowBase * KB_A;
    const char* bW = (const char*)W;

    float acc[4][4][4];
    #pragma unroll
    for (int i = 0; i < 4; ++i)
        #pragma unroll
        for (int j = 0; j < 4; ++j)
            #pragma unroll
            for (int k = 0; k < 4; ++k) acc[i][j][k] = 0.0f;

    auto load_chunk = [&](int ck, int s) {
        if (ck < NCC) {
            const uint32_t st = sb + (uint32_t)s * STAGE;
            // plane-mapped A byte offset within row
            const int pc = (ck >= 2 * KC) ? (ck - 2 * KC) : (ck >= KC ? ck - KC : ck);
            const int aoff = ((ck >= 2 * KC) ? 2 * K : 0) + pc * 128;
            const int woff = ck * 128;
            #pragma unroll
            for (int j = 0; j < 2; ++j) {                // A: 128 rows x 8x16B
                int v = tid + j * 512;
                int row = v >> 3, c = v & 7;
                cp16(st + row * LD + c * 16, bA + (size_t)row * KB_A + aoff + c * 16);
            }
            #pragma unroll
            for (int j = 0; j < 4; ++j) {                // W: 256 rows x 8x16B
                int v = tid + j * 512;
                int row = v >> 3, c = v & 7;
                cp16(st + A_SZ + row * LD + c * 16, bW + (size_t)row * KB_W + woff + c * 16);
            }
        }
        asm volatile("cp.async.commit_group;" ::: "memory");
    };

    load_chunk(0, 0);
    load_chunk(1, 1);
    load_chunk(2, 2);

    const int a_row = (lane & 15);
    const int a_k8  = (lane >> 4) << 3;
    const int b_row = (lane & 7) + ((lane >> 4) << 3);
    const int b_k8  = ((lane >> 3) & 1) << 3;

    for (int ck = 0; ck < NCC; ++ck) {
        const int s = ck % 3;
        asm volatile("cp.async.wait_group 2;" ::: "memory");
        __syncthreads();

        const uint32_t aA = sb + (uint32_t)s * STAGE;
        const uint32_t aW = aA + A_SZ;

        #pragma unroll
        for (int kk = 0; kk < 4; ++kk) {
            const uint32_t kbA = (uint32_t)((kk * 16 + a_k8) * 2);
            const uint32_t kbB = (uint32_t)((kk * 16 + b_k8) * 2);

            uint32_t bb[8];
            #pragma unroll
            for (int g = 0; g < 2; ++g) {
                uint32_t nn = (uint32_t)(warp_n * 32 + g * 16 + b_row);
                ldsm_x4(bb + g * 4, aW + nn * LD + kbB);
            }
            #pragma unroll
            for (int mt = 0; mt < 4; ++mt) {
                uint32_t m = (uint32_t)(warp_m * 64 + mt * 16 + a_row);
                uint32_t aa[4];
                ldsm_x4(aa, aA + m * LD + kbA);
                #pragma unroll
                for (int nt = 0; nt < 4; ++nt)
                    mma16816(acc[mt][nt], aa, bb + nt * 2);
            }
        }

        __syncthreads();
        load_chunk(ck + 3, s);
    }

    // ---- Epilogue 1: write Y ----
    const int er = lane >> 2;
    const int ec = (lane & 3) * 2;
    #pragma unroll
    for (int mt = 0; mt < 4; ++mt) {
        const int row = rowBase + warp_m * 64 + mt * 16 + er;
        #pragma unroll
        for (int nt = 0; nt < 4; ++nt) {
            const int col = warp_n * 32 + nt * 8 + ec;
            *(float2*)(Y + (size_t)row * CH + col) =
                make_float2(acc[mt][nt][0], acc[mt][nt][1]);
            *(float2*)(Y + (size_t)(row + 8) * CH + col) =
                make_float2(acc[mt][nt][2], acc[mt][nt][3]);
        }
    }

    // ---- Epilogue 2: fused BN stats (sum, sumsq per channel) ----
    // Each thread owns channels {warp_n*32 + nt*8 + ec + j} for rows
    // {er, er+8} x 4 m-tiles. Reduce over the 4 lanes sharing a channel
    // (lane quads 0,4,8,...), then atomically add per warp.
    #pragma unroll
    for (int nt = 0; nt < 4; ++nt) {
        #pragma unroll
        for (int j = 0; j < 2; ++j) {
            float s = 0.0f, q = 0.0f;
            #pragma unroll
            for (int mt = 0; mt < 4; ++mt) {
                float u0 = acc[mt][nt][j];
                float u1 = acc[mt][nt][j + 2];
                s += u0 + u1;
                q = fmaf(u0, u0, q);
                q = fmaf(u1, u1, q);
            }
            s += __shfl_down_sync(0xffffffffu, s, 16);
            q += __shfl_down_sync(0xffffffffu, q, 16);
            s += __shfl_down_sync(0xffffffffu, s, 8);
            q += __shfl_down_sync(0xffffffffu, q, 8);
            s += __shfl_down_sync(0xffffffffu, s, 4);
            q += __shfl_down_sync(0xffffffffu, q, 4);
            if ((lane >> 2) == 0) {
                int col = warp_n * 32 + nt * 8 + ec + j;
                atomicAdd(&stats[col], s);
                atomicAdd(&stats[CH + col], q);
            }
        }
    }
}

// ---------------------------------------------------------------------------
// BN+ReLU, output 2-plane bf16 (layer1 -> layer2 input)
// ---------------------------------------------------------------------------
__global__ void __launch_bounds__(256) bnrelu_split_kernel(
    const float* __restrict__ Y,
    const float* __restrict__ gamma, const float* __restrict__ beta,
    __nv_bfloat16* __restrict__ X)
{
    __shared__ float sc[CH], bi[CH];
    const int t = threadIdx.x;
    {
        const float invM = 1.0f / (float)ROWS;
        float mean = g_stats1[t] * invM;
        float var  = g_stats1[CH + t] * invM - mean * mean;
        float s = rsqrtf(var + 1e-5f) * gamma[t];
        sc[t] = s;
        bi[t] = beta[t] - mean * s;
    }
    __syncthreads();

    const int total = ROWS * CH / 4;
    for (int i = blockIdx.x * 256 + t; i < total; i += gridDim.x * 256) {
        float4 v = ((const float4*)Y)[i];
        int row = i >> 6;
        int c0 = (i & 63) * 4;
        float o[4];
        o[0] = fmaxf(fmaf(v.x, sc[c0+0], bi[c0+0]), 0.0f);
        o[1] = fmaxf(fmaf(v.y, sc[c0+1], bi[c0+1]), 0.0f);
        o[2] = fmaxf(fmaf(v.z, sc[c0+2], bi[c0+2]), 0.0f);
        o[3] = fmaxf(fmaf(v.w, sc[c0+3], bi[c0+3]), 0.0f);
        __nv_bfloat16 h[4], l[4];
        #pragma unroll
        for (int j = 0; j < 4; ++j) split_bf16(o[j], h[j], l[j]);
        __nv_bfloat16* base = X + (size_t)row * (2 * CH) + c0;
        *(__nv_bfloat162*)(base)          = __halves2bfloat162(h[0], h[1]);
        *(__nv_bfloat162*)(base + 2)      = __halves2bfloat162(h[2], h[3]);
        *(__nv_bfloat162*)(base + CH)     = __halves2bfloat162(l[0], l[1]);
        *(__nv_bfloat162*)(base + CH + 2) = __halves2bfloat162(l[2], l[3]);
    }
}

// ---------------------------------------------------------------------------
// BN+ReLU in place (layer2 final, fp32)
// ---------------------------------------------------------------------------
__global__ void __launch_bounds__(256) bnrelu_inplace_kernel(
    float* __restrict__ X,
    const float* __restrict__ gamma, const float* __restrict__ beta)
{
    __shared__ float sc[CH], bi[CH];
    const int t = threadIdx.x;
    {
        const float invM = 1.0f / (float)ROWS;
        float mean = g_stats2[t] * invM;
        float var  = g_stats2[CH + t] * invM - mean * mean;
        float s = rsqrtf(var + 1e-5f) * gamma[t];
        sc[t] = s;
        bi[t] = beta[t] - mean * s;
    }
    __syncthreads();

    const int total = ROWS * CH / 4;
    for (int i = blockIdx.x * 256 + t; i < total; i += gridDim.x * 256) {
        float4 v = ((float4*)X)[i];
        int c0 = (i * 4) & (CH - 1);
        v.x = fmaxf(fmaf(v.x, sc[c0+0], bi[c0+0]), 0.0f);
        v.y = fmaxf(fmaf(v.y, sc[c0+1], bi[c0+1]), 0.0f);
        v.z = fmaxf(fmaf(v.z, sc[c0+2], bi[c0+2]), 0.0f);
        v.w = fmaxf(fmaf(v.w, sc[c0+3], bi[c0+3]), 0.0f);
        ((float4*)X)[i] = v;
    }
}

// ---------------------------------------------------------------------------
// Launcher (graph-capturable). gemm1 is launch index 3 (ncu capture target).
// ---------------------------------------------------------------------------
extern "C" void kernel_launch(void* const* d_in, const int* in_sizes, int n_in,
                              void* d_out, int out_size)
{
    const float* p1     = (const float*)d_in[0];
    const float* p2     = (const float*)d_in[1];
    const float* pf1    = (const float*)d_in[2];
    const float* pf2    = (const float*)d_in[3];
    const float* W1     = (const float*)d_in[4];
    const float* gamma1 = (const float*)d_in[5];
    const float* beta1  = (const float*)d_in[6];
    const float* W2     = (const float*)d_in[7];
    const float* gamma2 = (const float*)d_in[8];
    const float* beta2  = (const float*)d_in[9];
    float* out = (float*)d_out;

    __nv_bfloat16 *a1, *x, *w1, *w2;
    float *y, *st1, *st2;
    cudaGetSymbolAddress((void**)&a1, g_a1);
    cudaGetSymbolAddress((void**)&x,  g_x);
    cudaGetSymbolAddress((void**)&w1, g_w1);
    cudaGetSymbolAddress((void**)&w2, g_w2);
    cudaGetSymbolAddress((void**)&y,  g_y);
    cudaGetSymbolAddress((void**)&st1, g_stats1);
    cudaGetSymbolAddress((void**)&st2, g_stats2);

    const int GEMM_SMEM = 3 * 55296;   // 165888 bytes
    cudaFuncSetAttribute(gemm_fused_kernel<CIN>,
                         cudaFuncAttributeMaxDynamicSharedMemorySize, GEMM_SMEM);
    cudaFuncSetAttribute(gemm_fused_kernel<CH>,
                         cudaFuncAttributeMaxDynamicSharedMemorySize, GEMM_SMEM);

    // idx0: W1 conversion + stats zeroing
    conv_w1_zero_kernel<<<(CH * CIN + 255) / 256, 256>>>(W1, w1);
    // idx1: pf1 -> 2-plane
    conv_pf1_kernel<<<ROWS * C1 / 4 / 256, 256>>>(pf1, a1);
    // idx2: KNN + interp -> 2-plane
    knn_interp_kernel<<<dim3(NPTS / 256, BB), 256>>>(p1, p2, pf2, a1);
    // idx3: layer-1 GEMM (ncu capture lands here)
    gemm_fused_kernel<CIN><<<ROWS / 128, 512, GEMM_SMEM>>>(a1, w1, y, st1);
    // idx4: W2 conversion
    conv_w2_kernel<<<(CH * CH + 255) / 256, 256>>>(W2, w2);
    // idx5: BN+ReLU -> 2-plane x
    bnrelu_split_kernel<<<2048, 256>>>(y, gamma1, beta1, x);
    // idx6: layer-2 GEMM -> d_out (pre-activation)
    gemm_fused_kernel<CH><<<ROWS / 128, 512, GEMM_SMEM>>>(x, w2, out, st2);
    // idx7: final BN+ReLU in place
    bnrelu_inplace_kernel<<<2048, 256>>>(out, gamma2, beta2);
}

// round 7
// speedup vs baseline: 1.6284x; 1.0970x over previous
#include <cuda_runtime.h>
#include <cuda_bf16.h>
#include <cstdint>

#define BB   4
#define NPTS 16384
#define SSZ  2048
#define C1   128
#define C2   256
#define CIN  384
#define CH   256
#define ROWS (BB*NPTS)   // 65536

// ---------------------------------------------------------------------------
// Scratch. A-side: 2 planes per row [hi(K) | lo(K)].
// W-side: 3 planes per row [hi(K) | lo(K) | hi(K)].
// GEMM chunk map: ck in [0,KC): Ahi*Whi; [KC,2KC): Ahi*Wlo; [2KC,3KC): Alo*Whi.
// ---------------------------------------------------------------------------
__device__ __nv_bfloat16 g_a1[(size_t)ROWS * 2 * CIN];  // 100 MB
__device__ __nv_bfloat16 g_x [(size_t)ROWS * 2 * CH];   // 67 MB
__device__ float         g_y [(size_t)ROWS * CH];       // 67 MB
__device__ __nv_bfloat16 g_w1[CH * 3 * CIN];
__device__ __nv_bfloat16 g_w2[CH * 3 * CH];
__device__ float g_stats1[2 * CH];
__device__ float g_stats2[2 * CH];

// ---------------------------------------------------------------------------
// PTX helpers (compute_103-safe)
// ---------------------------------------------------------------------------
__device__ __forceinline__ uint32_t smem_u32(const void* p) {
    uint32_t a;
    asm("{ .reg .u64 t; cvta.to.shared.u64 t, %1; cvt.u32.u64 %0, t; }"
        : "=r"(a) : "l"(p));
    return a;
}

__device__ __forceinline__ void cp16(uint32_t dst, const void* src) {
    asm volatile("cp.async.cg.shared.global [%0], [%1], 16;" :: "r"(dst), "l"(src));
}

__device__ __forceinline__ void ldsm_x4(uint32_t* r, uint32_t addr) {
    asm volatile("ldmatrix.sync.aligned.m8n8.x4.shared.b16 {%0,%1,%2,%3}, [%4];"
        : "=r"(r[0]), "=r"(r[1]), "=r"(r[2]), "=r"(r[3]) : "r"(addr));
}

__device__ __forceinline__ void mma16816(float* d, const uint32_t* a, const uint32_t* b) {
    asm volatile(
        "mma.sync.aligned.m16n8k16.row.col.f32.bf16.bf16.f32 "
        "{%0,%1,%2,%3}, {%4,%5,%6,%7}, {%8,%9}, {%0,%1,%2,%3};"
        : "+f"(d[0]), "+f"(d[1]), "+f"(d[2]), "+f"(d[3])
        : "r"(a[0]), "r"(a[1]), "r"(a[2]), "r"(a[3]), "r"(b[0]), "r"(b[1]));
}

__device__ __forceinline__ void split_bf16(float o, __nv_bfloat16& h, __nv_bfloat16& l) {
    h = __float2bfloat16(o);
    l = __float2bfloat16(o - __bfloat162float(h));
}

// ---------------------------------------------------------------------------
// W1 -> 3-plane [hi|lo|hi], plus zero both stats arrays (block 0).
// ---------------------------------------------------------------------------
__global__ void __launch_bounds__(256) conv_w1_zero_kernel(
    const float* __restrict__ W, __nv_bfloat16* __restrict__ out)
{
    if (blockIdx.x == 0) {
        g_stats1[threadIdx.x] = 0.0f;
        g_stats1[256 + threadIdx.x] = 0.0f;
        g_stats2[threadIdx.x] = 0.0f;
        g_stats2[256 + threadIdx.x] = 0.0f;
    }
    int i = blockIdx.x * 256 + threadIdx.x;
    if (i < CH * CIN) {
        int o = i / CIN, k = i % CIN;
        float w = W[i];
        __nv_bfloat16 h, l;
        split_bf16(w, h, l);
        __nv_bfloat16* base = out + (size_t)o * (3 * CIN) + k;
        base[0]       = h;
        base[CIN]     = l;
        base[2 * CIN] = h;
    }
}

__global__ void __launch_bounds__(256) conv_w2_kernel(
    const float* __restrict__ W, __nv_bfloat16* __restrict__ out)
{
    int i = blockIdx.x * 256 + threadIdx.x;
    if (i < CH * CH) {
        int o = i / CH, k = i % CH;
        float w = W[i];
        __nv_bfloat16 h, l;
        split_bf16(w, h, l);
        __nv_bfloat16* base = out + (size_t)o * (3 * CH) + k;
        base[0]      = h;
        base[CH]     = l;
        base[2 * CH] = h;
    }
}

// ---------------------------------------------------------------------------
// pf1 -> 2-plane cols [0,128) of g_a1  (row stride 2*CIN elems)
// ---------------------------------------------------------------------------
__global__ void __launch_bounds__(256) conv_pf1_kernel(
    const float* __restrict__ pf1, __nv_bfloat16* __restrict__ a1)
{
    int i = blockIdx.x * 256 + threadIdx.x;      // float4 index over ROWS*C1/4
    int row = i >> 5;
    int c4 = (i & 31) * 4;
    float4 v = ((const float4*)pf1)[i];
    float o[4] = {v.x, v.y, v.z, v.w};
    __nv_bfloat16 h[4], l[4];
    #pragma unroll
    for (int j = 0; j < 4; ++j) split_bf16(o[j], h[j], l[j]);
    __nv_bfloat16* base = a1 + (size_t)row * (2 * CIN) + c4;
    *(__nv_bfloat162*)(base)           = __halves2bfloat162(h[0], h[1]);
    *(__nv_bfloat162*)(base + 2)       = __halves2bfloat162(h[2], h[3]);
    *(__nv_bfloat162*)(base + CIN)     = __halves2bfloat162(l[0], l[1]);
    *(__nv_bfloat162*)(base + CIN + 2) = __halves2bfloat162(l[2], l[3]);
}

// ---------------------------------------------------------------------------
// KNN (k=3) + IDW interpolation -> 2-plane cols [128,384) of g_a1
// ---------------------------------------------------------------------------
__global__ void __launch_bounds__(256) knn_interp_kernel(
    const float* __restrict__ p1, const float* __restrict__ p2,
    const float* __restrict__ pf2, __nv_bfloat16* __restrict__ a1)
{
    __shared__ float4 sp[SSZ];
    const int b = blockIdx.y;
    const int tid = threadIdx.x;

    for (int i = tid; i < SSZ; i += 256) {
        float x = p2[(b * SSZ + i) * 3 + 0];
        float y = p2[(b * SSZ + i) * 3 + 1];
        float z = p2[(b * SSZ + i) * 3 + 2];
        sp[i] = make_float4(x, y, z, x*x + y*y + z*z);
    }
    __syncthreads();

    const int n = blockIdx.x * 256 + tid;
    const int q = b * NPTS + n;
    const float qx = p1[q*3+0], qy = p1[q*3+1], qz = p1[q*3+2];
    const float sq1 = qx*qx + qy*qy + qz*qz;

    float d0 = 1e30f, d1 = 1e30f, d2 = 1e30f;
    int   i0 = 0,     i1 = 0,     i2 = 0;

    #pragma unroll 4
    for (int s = 0; s < SSZ; ++s) {
        float4 t = sp[s];
        float dot = fmaf(qx, t.x, fmaf(qy, t.y, qz * t.z));
        float d = sq1 + t.w - 2.0f * dot;
        if (d < d2) {
            if (d < d1) {
                d2 = d1; i2 = i1;
                if (d < d0) { d1 = d0; i1 = i0; d0 = d; i0 = s; }
                else        { d1 = d;  i1 = s; }
            } else { d2 = d; i2 = s; }
        }
    }

    float r0 = 1.0f / (d0 + 1e-8f);
    float r1 = 1.0f / (d1 + 1e-8f);
    float r2 = 1.0f / (d2 + 1e-8f);
    float inv = 1.0f / (r0 + r1 + r2);
    float w0 = r0 * inv, w1 = r1 * inv, w2 = r2 * inv;

    const float4* f0 = (const float4*)(pf2 + (size_t)(b * SSZ + i0) * C2);
    const float4* f1 = (const float4*)(pf2 + (size_t)(b * SSZ + i1) * C2);
    const float4* f2 = (const float4*)(pf2 + (size_t)(b * SSZ + i2) * C2);
    __nv_bfloat16* base = a1 + (size_t)q * (2 * CIN) + C1;

    #pragma unroll 8
    for (int c = 0; c < C2 / 4; ++c) {
        float4 a = f0[c], bv = f1[c], cv = f2[c];
        float o[4];
        o[0] = w0*a.x + w1*bv.x + w2*cv.x;
        o[1] = w0*a.y + w1*bv.y + w2*cv.y;
        o[2] = w0*a.z + w1*bv.z + w2*cv.z;
        o[3] = w0*a.w + w1*bv.w + w2*cv.w;
        __nv_bfloat16 h[4], l[4];
        #pragma unroll
        for (int j = 0; j < 4; ++j) split_bf16(o[j], h[j], l[j]);
        *(__nv_bfloat162*)(base + c*4)           = __halves2bfloat162(h[0], h[1]);
        *(__nv_bfloat162*)(base + c*4 + 2)       = __halves2bfloat162(h[2], h[3]);
        *(__nv_bfloat162*)(base + CIN + c*4)     = __halves2bfloat162(l[0], l[1]);
        *(__nv_bfloat162*)(base + CIN + c*4 + 2) = __halves2bfloat162(l[2], l[3]);
    }
}

// ---------------------------------------------------------------------------
// bf16 pipelined GEMM, plane-mapped chunks, fused BN-stats epilogue.
// CTA tile 128x128, 256 threads (8 warps 2x4), warp tile 64x32.
// 3-stage cp.async, 110.6KB SMEM -> 2 CTAs/SM.
// ---------------------------------------------------------------------------
template <int K>
__global__ void __launch_bounds__(256, 2) gemm_fused_kernel(
    const __nv_bfloat16* __restrict__ A, const __nv_bfloat16* __restrict__ W,
    float* __restrict__ Y, float* __restrict__ stats)
{
    constexpr int KC  = K / 64;          // chunks per plane product
    constexpr int NCC = 3 * KC;          // total chunks
    constexpr int KB_A = 4 * K;          // A row stride bytes (hi+lo)
    constexpr int KB_W = 6 * K;          // W row stride bytes (3 planes)
    constexpr int LD = 144;              // smem row stride bytes
    constexpr int A_SZ = 128 * LD;       // 18432
    constexpr int W_SZ = 128 * LD;       // 18432
    constexpr int STAGE = A_SZ + W_SZ;   // 36864

    extern __shared__ char smem[];
    const uint32_t sb = smem_u32(smem);
    const int tid  = threadIdx.x;
    const int wid  = tid >> 5;
    const int lane = tid & 31;
    const int rowBase = blockIdx.x * 128;
    const int colBase = blockIdx.y * 128;

    const int warp_m = wid & 1;          // 64 rows each
    const int warp_n = wid >> 1;         // 0..3, 32 cols each

    const char* bA = (const char*)A + (size_t)rowBase * KB_A;
    const char* bW = (const char*)W + (size_t)colBase * KB_W;

    float acc[4][4][4];
    #pragma unroll
    for (int i = 0; i < 4; ++i)
        #pragma unroll
        for (int j = 0; j < 4; ++j)
            #pragma unroll
            for (int k = 0; k < 4; ++k) acc[i][j][k] = 0.0f;

    auto load_chunk = [&](int ck, int s) {
        if (ck < NCC) {
            const uint32_t st = sb + (uint32_t)s * STAGE;
            const int pc = (ck >= 2 * KC) ? (ck - 2 * KC) : (ck >= KC ? ck - KC : ck);
            const int aoff = ((ck >= 2 * KC) ? 2 * K : 0) + pc * 128;
            const int woff = ck * 128;
            #pragma unroll
            for (int j = 0; j < 4; ++j) {                // A: 128 rows x 8x16B
                int v = tid + j * 256;
                int row = v >> 3, c = v & 7;
                cp16(st + row * LD + c * 16, bA + (size_t)row * KB_A + aoff + c * 16);
            }
            #pragma unroll
            for (int j = 0; j < 4; ++j) {                // W: 128 rows x 8x16B
                int v = tid + j * 256;
                int row = v >> 3, c = v & 7;
                cp16(st + A_SZ + row * LD + c * 16, bW + (size_t)row * KB_W + woff + c * 16);
            }
        }
        asm volatile("cp.async.commit_group;" ::: "memory");
    };

    load_chunk(0, 0);
    load_chunk(1, 1);
    load_chunk(2, 2);

    const int a_row = (lane & 15);
    const int a_k8  = (lane >> 4) << 3;
    const int b_row = (lane & 7) + ((lane >> 4) << 3);
    const int b_k8  = ((lane >> 3) & 1) << 3;

    for (int ck = 0; ck < NCC; ++ck) {
        const int s = ck % 3;
        asm volatile("cp.async.wait_group 2;" ::: "memory");
        __syncthreads();

        const uint32_t aA = sb + (uint32_t)s * STAGE;
        const uint32_t aW = aA + A_SZ;

        #pragma unroll
        for (int kk = 0; kk < 4; ++kk) {
            const uint32_t kbA = (uint32_t)((kk * 16 + a_k8) * 2);
            const uint32_t kbB = (uint32_t)((kk * 16 + b_k8) * 2);

            uint32_t bb[8];
            #pragma unroll
            for (int g = 0; g < 2; ++g) {
                uint32_t nn = (uint32_t)(warp_n * 32 + g * 16 + b_row);
                ldsm_x4(bb + g * 4, aW + nn * LD + kbB);
            }
            #pragma unroll
            for (int mt = 0; mt < 4; ++mt) {
                uint32_t m = (uint32_t)(warp_m * 64 + mt * 16 + a_row);
                uint32_t aa[4];
                ldsm_x4(aa, aA + m * LD + kbA);
                #pragma unroll
                for (int nt = 0; nt < 4; ++nt)
                    mma16816(acc[mt][nt], aa, bb + nt * 2);
            }
        }

        __syncthreads();
        load_chunk(ck + 3, s);
    }

    // ---- Epilogue 1: write Y ----
    const int er = lane >> 2;
    const int ec = (lane & 3) * 2;
    #pragma unroll
    for (int mt = 0; mt < 4; ++mt) {
        const int row = rowBase + warp_m * 64 + mt * 16 + er;
        #pragma unroll
        for (int nt = 0; nt < 4; ++nt) {
            const int col = colBase + warp_n * 32 + nt * 8 + ec;
            *(float2*)(Y + (size_t)row * CH + col) =
                make_float2(acc[mt][nt][0], acc[mt][nt][1]);
            *(float2*)(Y + (size_t)(row + 8) * CH + col) =
                make_float2(acc[mt][nt][2], acc[mt][nt][3]);
        }
    }

    // ---- Epilogue 2: fused BN stats (sum, sumsq per channel) ----
    #pragma unroll
    for (int nt = 0; nt < 4; ++nt) {
        #pragma unroll
        for (int j = 0; j < 2; ++j) {
            float s = 0.0f, q = 0.0f;
            #pragma unroll
            for (int mt = 0; mt < 4; ++mt) {
                float u0 = acc[mt][nt][j];
                float u1 = acc[mt][nt][j + 2];
                s += u0 + u1;
                q = fmaf(u0, u0, q);
                q = fmaf(u1, u1, q);
            }
            s += __shfl_down_sync(0xffffffffu, s, 16);
            q += __shfl_down_sync(0xffffffffu, q, 16);
            s += __shfl_down_sync(0xffffffffu, s, 8);
            q += __shfl_down_sync(0xffffffffu, q, 8);
            s += __shfl_down_sync(0xffffffffu, s, 4);
            q += __shfl_down_sync(0xffffffffu, q, 4);
            if ((lane >> 2) == 0) {
                int col = colBase + warp_n * 32 + nt * 8 + ec + j;
                atomicAdd(&stats[col], s);
                atomicAdd(&stats[CH + col], q);
            }
        }
    }
}

// ---------------------------------------------------------------------------
// BN+ReLU, output 2-plane bf16 (layer1 -> layer2 input)
// ---------------------------------------------------------------------------
__global__ void __launch_bounds__(256) bnrelu_split_kernel(
    const float* __restrict__ Y,
    const float* __restrict__ gamma, const float* __restrict__ beta,
    __nv_bfloat16* __restrict__ X)
{
    __shared__ float sc[CH], bi[CH];
    const int t = threadIdx.x;
    {
        const float invM = 1.0f / (float)ROWS;
        float mean = g_stats1[t] * invM;
        float var  = g_stats1[CH + t] * invM - mean * mean;
        float s = rsqrtf(var + 1e-5f) * gamma[t];
        sc[t] = s;
        bi[t] = beta[t] - mean * s;
    }
    __syncthreads();

    const int total = ROWS * CH / 4;
    for (int i = blockIdx.x * 256 + t; i < total; i += gridDim.x * 256) {
        float4 v = ((const float4*)Y)[i];
        int row = i >> 6;
        int c0 = (i & 63) * 4;
        float o[4];
        o[0] = fmaxf(fmaf(v.x, sc[c0+0], bi[c0+0]), 0.0f);
        o[1] = fmaxf(fmaf(v.y, sc[c0+1], bi[c0+1]), 0.0f);
        o[2] = fmaxf(fmaf(v.z, sc[c0+2], bi[c0+2]), 0.0f);
        o[3] = fmaxf(fmaf(v.w, sc[c0+3], bi[c0+3]), 0.0f);
        __nv_bfloat16 h[4], l[4];
        #pragma unroll
        for (int j = 0; j < 4; ++j) split_bf16(o[j], h[j], l[j]);
        __nv_bfloat16* base = X + (size_t)row * (2 * CH) + c0;
        *(__nv_bfloat162*)(base)          = __halves2bfloat162(h[0], h[1]);
        *(__nv_bfloat162*)(base + 2)      = __halves2bfloat162(h[2], h[3]);
        *(__nv_bfloat162*)(base + CH)     = __halves2bfloat162(l[0], l[1]);
        *(__nv_bfloat162*)(base + CH + 2) = __halves2bfloat162(l[2], l[3]);
    }
}

// ---------------------------------------------------------------------------
// BN+ReLU in place (layer2 final, fp32)
// ---------------------------------------------------------------------------
__global__ void __launch_bounds__(256) bnrelu_inplace_kernel(
    float* __restrict__ X,
    const float* __restrict__ gamma, const float* __restrict__ beta)
{
    __shared__ float sc[CH], bi[CH];
    const int t = threadIdx.x;
    {
        const float invM = 1.0f / (float)ROWS;
        float mean = g_stats2[t] * invM;
        float var  = g_stats2[CH + t] * invM - mean * mean;
        float s = rsqrtf(var + 1e-5f) * gamma[t];
        sc[t] = s;
        bi[t] = beta[t] - mean * s;
    }
    __syncthreads();

    const int total = ROWS * CH / 4;
    for (int i = blockIdx.x * 256 + t; i < total; i += gridDim.x * 256) {
        float4 v = ((float4*)X)[i];
        int c0 = (i * 4) & (CH - 1);
        v.x = fmaxf(fmaf(v.x, sc[c0+0], bi[c0+0]), 0.0f);
        v.y = fmaxf(fmaf(v.y, sc[c0+1], bi[c0+1]), 0.0f);
        v.z = fmaxf(fmaf(v.z, sc[c0+2], bi[c0+2]), 0.0f);
        v.w = fmaxf(fmaf(v.w, sc[c0+3], bi[c0+3]), 0.0f);
        ((float4*)X)[i] = v;
    }
}

// ---------------------------------------------------------------------------
// Launcher (graph-capturable). gemm1 is launch index 3 (ncu capture target).
// ---------------------------------------------------------------------------
extern "C" void kernel_launch(void* const* d_in, const int* in_sizes, int n_in,
                              void* d_out, int out_size)
{
    const float* p1     = (const float*)d_in[0];
    const float* p2     = (const float*)d_in[1];
    const float* pf1    = (const float*)d_in[2];
    const float* pf2    = (const float*)d_in[3];
    const float* W1     = (const float*)d_in[4];
    const float* gamma1 = (const float*)d_in[5];
    const float* beta1  = (const float*)d_in[6];
    const float* W2     = (const float*)d_in[7];
    const float* gamma2 = (const float*)d_in[8];
    const float* beta2  = (const float*)d_in[9];
    float* out = (float*)d_out;

    __nv_bfloat16 *a1, *x, *w1, *w2;
    float *y, *st1, *st2;
    cudaGetSymbolAddress((void**)&a1, g_a1);
    cudaGetSymbolAddress((void**)&x,  g_x);
    cudaGetSymbolAddress((void**)&w1, g_w1);
    cudaGetSymbolAddress((void**)&w2, g_w2);
    cudaGetSymbolAddress((void**)&y,  g_y);
    cudaGetSymbolAddress((void**)&st1, g_stats1);
    cudaGetSymbolAddress((void**)&st2, g_stats2);

    const int GEMM_SMEM = 3 * 36864;   // 110592 bytes -> 2 CTAs/SM
    cudaFuncSetAttribute(gemm_fused_kernel<CIN>,
                         cudaFuncAttributeMaxDynamicSharedMemorySize, GEMM_SMEM);
    cudaFuncSetAttribute(gemm_fused_kernel<CH>,
                         cudaFuncAttributeMaxDynamicSharedMemorySize, GEMM_SMEM);

    // idx0: W1 conversion + stats zeroing
    conv_w1_zero_kernel<<<(CH * CIN + 255) / 256, 256>>>(W1, w1);
    // idx1: pf1 -> 2-plane
    conv_pf1_kernel<<<ROWS * C1 / 4 / 256, 256>>>(pf1, a1);
    // idx2: KNN + interp -> 2-plane
    knn_interp_kernel<<<dim3(NPTS / 256, BB), 256>>>(p1, p2, pf2, a1);
    // idx3: layer-1 GEMM (ncu capture lands here)
    gemm_fused_kernel<CIN><<<dim3(ROWS / 128, CH / 128), 256, GEMM_SMEM>>>(a1, w1, y, st1);
    // idx4: W2 conversion
    conv_w2_kernel<<<(CH * CH + 255) / 256, 256>>>(W2, w2);
    // idx5: BN+ReLU -> 2-plane x
    bnrelu_split_kernel<<<2048, 256>>>(y, gamma1, beta1, x);
    // idx6: layer-2 GEMM -> d_out (pre-activation)
    gemm_fused_kernel<CH><<<dim3(ROWS / 128, CH / 128), 256, GEMM_SMEM>>>(x, w2, out, st2);
    // idx7: final BN+ReLU in place
    bnrelu_inplace_kernel<<<2048, 256>>>(out, gamma2, beta2);
}